// round 5
// baseline (speedup 1.0000x reference)
#include <cuda_runtime.h>
#include <math.h>

// Problem constants
#define NBATCH 4
#define NID    16
#define NPAIR  (NBATCH*NID)
#define DD     32
#define HH     192
#define WW     192
#define DHW    (DD*HH*WW)          // 1179648
#define CHUNK  4096
#define NCHUNK (DHW/CHUNK)         // 288 exactly
#define NB     65536               // histogram bins over e in [0,2]
#define INV_W  32768.0f            // 1 / bin_width  (bin_width = 2/65536)

#define INV_WM1 (1.0f/(WW-1))
#define INV_HM1 (1.0f/(HH-1))
#define INV_DM1 (1.0f/(DD-1))

// ---------------- scratch (static device globals; no allocation) ----------------
__device__ unsigned g_negH[(size_t)NPAIR * NB];   // 16 MB
__device__ unsigned g_posH[(size_t)NPAIR * NB];   // 16 MB
__device__ float  g_acc[NPAIR][10];   // cnt, sx,sy,sz, ss0..2, sq0..2
__device__ float  g_bg[NBATCH];
__device__ float  g_center[NPAIR][3];
__device__ float  g_sexp[NPAIR][3];
__device__ float  g_var[NPAIR];
__device__ float  g_exists[NPAIR];
__device__ float  g_seedl[NPAIR];
__device__ double g_instl[NPAIR];

__device__ __forceinline__ float sigmoidf_(float x) {
    return 1.0f / (1.0f + __expf(-x));
}

// decode linear voxel index -> normalized coords (matches jnp.linspace(0,1,n))
__device__ __forceinline__ void coords_(int v, float& x, float& y, float& z) {
    int w = v % WW;
    int r = v / WW;
    int h = r % HH;
    int d = r / HH;
    x = (float)w * INV_WM1;
    y = (float)h * INV_HM1;
    z = (float)d * INV_DM1;
}

// ---------------- K0: zero all accumulators / histograms ----------------
__global__ void k_zero() {
    const size_t n4 = (size_t)NPAIR * NB / 4;   // uint4 count per array
    uint4 z = make_uint4(0u, 0u, 0u, 0u);
    uint4* pn = reinterpret_cast<uint4*>(g_negH);
    uint4* pp = reinterpret_cast<uint4*>(g_posH);
    size_t stride = (size_t)gridDim.x * blockDim.x;
    for (size_t i = (size_t)blockIdx.x * blockDim.x + threadIdx.x; i < n4; i += stride) {
        pn[i] = z;
        pp[i] = z;
    }
    if (blockIdx.x == 0) {
        for (int t = threadIdx.x; t < NPAIR * 10; t += blockDim.x)
            g_acc[t / 10][t % 10] = 0.0f;
        for (int t = threadIdx.x; t < NBATCH; t += blockDim.x)
            g_bg[t] = 0.0f;
        for (int t = threadIdx.x; t < NPAIR; t += blockDim.x)
            g_seedl[t] = 0.0f;
    }
}

// ---------------- K1: per-(b,id) masked moments + background seed ----------------
// Direct global REDs (L2 atomic units) — cheaper than smem ATOMS on sm_103a.
__global__ void __launch_bounds__(256) k_stats(const float* __restrict__ pred,
                                               const int*   __restrict__ inst,
                                               const int*   __restrict__ labels) {
    __shared__ float accbg;
    int b = blockIdx.y;
    if (threadIdx.x == 0) accbg = 0.0f;
    __syncthreads();

    const float* pb = pred + (size_t)b * 7 * DHW;
    const int*   ib = inst + (size_t)b * DHW;
    const int*   lb = labels + (size_t)b * DHW;
    int base = blockIdx.x * CHUNK;
    int lane = threadIdx.x & 31;

    #pragma unroll 2
    for (int k = 0; k < CHUNK / 256; k++) {
        int v = base + k * 256 + threadIdx.x;
        float s0 = pb[3 * DHW + v];
        float s1 = pb[4 * DHW + v];
        float s2 = pb[5 * DHW + v];
        float sd = pb[6 * DHW + v];
        float seed = sigmoidf_(sd);
        int   ii = ib[v];
        int   lv = lb[v];

        // background seed: warp reduce then one smem atomic
        float bgv = (lv == 0) ? seed * seed : 0.0f;
        #pragma unroll
        for (int off = 16; off > 0; off >>= 1)
            bgv += __shfl_down_sync(0xffffffffu, bgv, off);
        if (lane == 0 && bgv != 0.0f) atomicAdd(&accbg, bgv);

        // per-id moments: direct global REDs, cnt aggregated via match+popc
        unsigned peers = __match_any_sync(0xffffffffu, ii);
        if (ii >= 1) {
            int id = ii - 1;
            float x, y, z;
            coords_(v, x, y, z);
            float* a = g_acc[b * NID + id];
            bool leader = (peers & ((1u << lane) - 1u)) == 0u;
            if (leader) atomicAdd(a + 0, (float)__popc(peers));
            atomicAdd(a + 1, x);
            atomicAdd(a + 2, y);
            atomicAdd(a + 3, z);
            atomicAdd(a + 4, s0);
            atomicAdd(a + 5, s1);
            atomicAdd(a + 6, s2);
            atomicAdd(a + 7, s0 * s0);
            atomicAdd(a + 8, s1 * s1);
            atomicAdd(a + 9, s2 * s2);
        }
    }
    __syncthreads();
    if (threadIdx.x == 0 && accbg != 0.0f) atomicAdd(&g_bg[b], accbg);
}

// ---------------- K2: finalize per-pair stats ----------------
__global__ void k_finalize() {
    int p = threadIdx.x;
    if (p >= NPAIR) return;
    float cnt  = g_acc[p][0];
    float ex   = (cnt > 0.0f) ? 1.0f : 0.0f;
    float safe = fmaxf(cnt, 1.0f);
    float var  = 0.0f;
    #pragma unroll
    for (int k = 0; k < 3; k++) {
        float c  = g_acc[p][1 + k] / safe;
        float mu = g_acc[p][4 + k] / safe;
        var += g_acc[p][7 + k] - cnt * mu * mu;
        g_center[p][k] = c;
        g_sexp[p][k]   = __expf(10.0f * mu);
    }
    g_var[p]    = ex * (var / (3.0f * safe));
    g_exists[p] = ex;
}

// ---------------- K3: fused dist / seed-loss / error-histogram pass ----------------
__global__ void __launch_bounds__(256) k_dist(const float* __restrict__ pred,
                                              const int*   __restrict__ inst) {
    __shared__ float sc[NID][8];     // cx,cy,cz, e0,e1,e2, exists, pad
    __shared__ float sseed[NID];
    int b = blockIdx.y;
    if (threadIdx.x < NID * 7) {
        int id = threadIdx.x / 7, c = threadIdx.x % 7;
        float v;
        if (c < 3)      v = g_center[b * NID + id][c];
        else if (c < 6) v = g_sexp[b * NID + id][c - 3];
        else            v = g_exists[b * NID + id];
        sc[id][c] = v;
    }
    if (threadIdx.x < NID) sseed[threadIdx.x] = 0.0f;
    __syncthreads();

    const float* pb = pred + (size_t)b * 7 * DHW;
    const int*   ib = inst + (size_t)b * DHW;
    unsigned* negH = g_negH + (size_t)b * NID * NB;
    unsigned* posH = g_posH + (size_t)b * NID * NB;
    int base = blockIdx.x * CHUNK;

    for (int k = 0; k < CHUNK / 256; k++) {
        int v = base + k * 256 + threadIdx.x;
        float x, y, z;
        coords_(v, x, y, z);
        float se0 = tanhf(pb[v])           + x;
        float se1 = tanhf(pb[DHW + v])     + y;
        float se2 = tanhf(pb[2 * DHW + v]) + z;
        float seed = sigmoidf_(pb[6 * DHW + v]);
        int   ii = ib[v];

        #pragma unroll
        for (int id = 0; id < NID; id++) {
            if (sc[id][6] == 0.0f) continue;
            float dx = se0 - sc[id][0];
            float dy = se1 - sc[id][1];
            float dz = se2 - sc[id][2];
            float t = fmaf(dx * dx, sc[id][3],
                      fmaf(dy * dy, sc[id][4],
                           dz * dz * sc[id][5]));
            float d = __expf(-t);
            bool pos = (ii == id + 1);
            float e = pos ? (2.0f - 2.0f * d) : (2.0f * d);
            int bin = (int)(e * INV_W);
            bin = min(bin, NB - 1);
            if (pos) {
                atomicAdd(&posH[id * NB + bin], 1u);
                float dv = seed - d;
                atomicAdd(&sseed[id], dv * dv);
            } else {
                atomicAdd(&negH[id * NB + bin], 1u);
            }
        }
    }
    __syncthreads();
    if (threadIdx.x < NID && sseed[threadIdx.x] != 0.0f)
        atomicAdd(&g_seedl[b * NID + threadIdx.x], sseed[threadIdx.x]);
}

// ---------------- K4: Lovasz via descending-bin scan (one block per pair) ----------------
__global__ void __launch_bounds__(256) k_lovasz() {
    int p = blockIdx.x;                         // 0..63
    __shared__ unsigned sp[256], sn[256];
    __shared__ unsigned op[257], on[257];
    __shared__ double  part[256];
    const unsigned* posH = g_posH + (size_t)p * NB;
    const unsigned* negH = g_negH + (size_t)p * NB;
    int t = threadIdx.x;
    const int CB = NB / 256;                    // 256 bins per thread

    // Phase 1: local sums over this thread's descending-e chunk
    unsigned lp = 0, ln = 0;
    for (int i = 0; i < CB; i++) {
        int bin = (NB - 1) - (t * CB + i);
        lp += posH[bin];
        ln += negH[bin];
    }
    sp[t] = lp; sn[t] = ln;
    __syncthreads();
    if (t == 0) {
        unsigned ap = 0, an = 0;
        for (int i = 0; i < 256; i++) { op[i] = ap; on[i] = an; ap += sp[i]; an += sn[i]; }
        op[256] = ap; on[256] = an;
    }
    __syncthreads();

    double contrib = 0.0;
    unsigned Pu = op[256];
    if (Pu > 0) {
        double P = (double)Pu;
        unsigned cp = op[t], cn = on[t];
        double Jprev = 1.0 - (P - (double)cp) / (P + (double)cn);  // = 0 when cp=cn=0
        for (int i = 0; i < CB; i++) {
            int bin = (NB - 1) - (t * CB + i);
            unsigned np = posH[bin], nn = negH[bin];
            if (np | nn) {
                cp += np; cn += nn;
                double J = 1.0 - (P - (double)cp) / (P + (double)cn);
                double eb = ((double)bin + 0.5) * (1.0 / 32768.0);
                contrib += eb * (J - Jprev);
                Jprev = J;
            }
        }
    }
    part[t] = contrib;
    __syncthreads();
    for (int s = 128; s > 0; s >>= 1) {
        if (t < s) part[t] += part[t + s];
        __syncthreads();
    }
    if (t == 0) g_instl[p] = part[0];
}

// ---------------- K5: assemble the 4 outputs ----------------
__global__ void k_final(float* __restrict__ out) {
    if (threadIdx.x != 0) return;
    double li = 0.0, lv = 0.0, ls = 0.0;
    for (int b = 0; b < NBATCH; b++) {
        double obj = 0.0, vv = 0.0, il = 0.0, sl = 0.0;
        for (int id = 0; id < NID; id++) {
            int p = b * NID + id;
            obj += (double)g_exists[p];
            vv  += (double)g_var[p];
            il  += g_instl[p];
            sl  += (double)g_seedl[p];
        }
        double denom = fmax(obj, 1.0);
        li += il / denom;
        lv += vv / denom;
        ls += (sl + (double)g_bg[b]) / (double)DHW;
    }
    li = li / NBATCH;                 // W_INST = 1
    lv = lv * 10.0 / NBATCH;          // W_VAR = 10
    ls = ls / NBATCH;                 // W_SEED = 1
    out[0] = (float)li;
    out[1] = (float)lv;
    out[2] = (float)ls;
    out[3] = (float)(li + lv + ls);
}

// ---------------- launch ----------------
extern "C" void kernel_launch(void* const* d_in, const int* in_sizes, int n_in,
                              void* d_out, int out_size) {
    const float* pred   = (const float*)d_in[0];   // (B,7,D,H,W)
    const int*   inst   = (const int*)d_in[1];     // (B,D,H,W)
    const int*   labels = (const int*)d_in[2];     // (B,D,H,W)
    // d_in[3] center_images — unused by the reference loss
    // d_in[4] xyzm — computed analytically on device now
    float* out = (float*)d_out;

    k_zero<<<2048, 256>>>();
    dim3 g(NCHUNK, NBATCH);
    k_stats<<<g, 256>>>(pred, inst, labels);
    k_finalize<<<1, 64>>>();
    k_dist<<<g, 256>>>(pred, inst);
    k_lovasz<<<NPAIR, 256>>>();
    k_final<<<1, 32>>>(out);
}

// round 6
// speedup vs baseline: 6.4374x; 6.4374x over previous
#include <cuda_runtime.h>
#include <math.h>

// Problem constants
#define NBATCH 4
#define NID    16
#define NPAIR  (NBATCH*NID)
#define DD     32
#define HH     192
#define WW     192
#define DHW    (DD*HH*WW)          // 1179648
#define CHUNK  4096
#define NCHUNK (DHW/CHUNK)         // 288 exactly
#define NB     65536               // histogram bins over e in [0,2]
#define INV_W  32768.0f            // 1 / bin_width  (bin_width = 2/65536)

#define INV_WM1 (1.0f/(WW-1))
#define INV_HM1 (1.0f/(HH-1))
#define INV_DM1 (1.0f/(DD-1))

// ---------------- scratch (static device globals; no allocation) ----------------
__device__ unsigned g_negH[(size_t)NPAIR * NB];   // 16 MB
__device__ unsigned g_posH[(size_t)NPAIR * NB];   // 16 MB
// per-CTA-private partial sums: [batch][id*10+slot][chunk-block]  (737 KB)
__device__ float  g_part[NBATCH][NID * 10][NCHUNK];
__device__ float  g_acc[NPAIR][10];   // cnt, sx,sy,sz, ss0..2, sq0..2
__device__ float  g_bg[NBATCH];
__device__ float  g_center[NPAIR][3];
__device__ float  g_sexp[NPAIR][3];
__device__ float  g_var[NPAIR];
__device__ float  g_exists[NPAIR];
__device__ float  g_seedl[NPAIR];
__device__ double g_instl[NPAIR];

__device__ __forceinline__ float sigmoidf_(float x) {
    return 1.0f / (1.0f + __expf(-x));
}

// decode linear voxel index -> normalized coords (matches jnp.linspace(0,1,n))
__device__ __forceinline__ void coords_(int v, float& x, float& y, float& z) {
    int w = v % WW;
    int r = v / WW;
    int h = r % HH;
    int d = r / HH;
    x = (float)w * INV_WM1;
    y = (float)h * INV_HM1;
    z = (float)d * INV_DM1;
}

// ---------------- K0: zero all accumulators / histograms ----------------
__global__ void k_zero() {
    const size_t n4 = (size_t)NPAIR * NB / 4;   // uint4 count per array
    uint4 z = make_uint4(0u, 0u, 0u, 0u);
    uint4* pn = reinterpret_cast<uint4*>(g_negH);
    uint4* pp = reinterpret_cast<uint4*>(g_posH);
    size_t stride = (size_t)gridDim.x * blockDim.x;
    size_t tid0 = (size_t)blockIdx.x * blockDim.x + threadIdx.x;
    for (size_t i = tid0; i < n4; i += stride) {
        pn[i] = z;
        pp[i] = z;
    }
    float* fp = &g_part[0][0][0];
    const size_t npart = (size_t)NBATCH * NID * 10 * NCHUNK;
    for (size_t i = tid0; i < npart; i += stride) fp[i] = 0.0f;
    if (blockIdx.x == 0) {
        for (int t = threadIdx.x; t < NPAIR * 10; t += blockDim.x)
            g_acc[t / 10][t % 10] = 0.0f;
        for (int t = threadIdx.x; t < NBATCH; t += blockDim.x)
            g_bg[t] = 0.0f;
        for (int t = threadIdx.x; t < NPAIR; t += blockDim.x)
            g_seedl[t] = 0.0f;
    }
}

// ---------------- K1: per-(b,id) masked moments + background seed ----------------
// Global REDs into per-CTA-private scratch rows: REDG spread-address throughput,
// zero cross-block address contention.
__global__ void __launch_bounds__(256) k_stats(const float* __restrict__ pred,
                                               const int*   __restrict__ inst,
                                               const int*   __restrict__ labels) {
    __shared__ float accbg;
    int b  = blockIdx.y;
    int bx = blockIdx.x;
    if (threadIdx.x == 0) accbg = 0.0f;
    __syncthreads();

    const float* pb = pred + (size_t)b * 7 * DHW;
    const int*   ib = inst + (size_t)b * DHW;
    const int*   lb = labels + (size_t)b * DHW;
    int base = bx * CHUNK;
    int lane = threadIdx.x & 31;
    float* part = &g_part[b][0][bx];     // stride between slots = NCHUNK floats

    #pragma unroll 2
    for (int k = 0; k < CHUNK / 256; k++) {
        int v = base + k * 256 + threadIdx.x;
        float s0 = pb[3 * DHW + v];
        float s1 = pb[4 * DHW + v];
        float s2 = pb[5 * DHW + v];
        float sd = pb[6 * DHW + v];
        float seed = sigmoidf_(sd);
        int   ii = ib[v];
        int   lv = lb[v];

        // background seed: warp reduce then one smem atomic
        float bgv = (lv == 0) ? seed * seed : 0.0f;
        #pragma unroll
        for (int off = 16; off > 0; off >>= 1)
            bgv += __shfl_down_sync(0xffffffffu, bgv, off);
        if (lane == 0 && bgv != 0.0f) atomicAdd(&accbg, bgv);

        // per-id moments into this CTA's private row; cnt via match+popc leader
        unsigned peers = __match_any_sync(0xffffffffu, ii);
        if (ii >= 1) {
            int id = ii - 1;
            float x, y, z;
            coords_(v, x, y, z);
            float* a = part + (size_t)(id * 10) * NCHUNK;
            bool leader = (peers & ((1u << lane) - 1u)) == 0u;
            if (leader) atomicAdd(a, (float)__popc(peers));
            atomicAdd(a + 1 * NCHUNK, x);
            atomicAdd(a + 2 * NCHUNK, y);
            atomicAdd(a + 3 * NCHUNK, z);
            atomicAdd(a + 4 * NCHUNK, s0);
            atomicAdd(a + 5 * NCHUNK, s1);
            atomicAdd(a + 6 * NCHUNK, s2);
            atomicAdd(a + 7 * NCHUNK, s0 * s0);
            atomicAdd(a + 8 * NCHUNK, s1 * s1);
            atomicAdd(a + 9 * NCHUNK, s2 * s2);
        }
    }
    __syncthreads();
    if (threadIdx.x == 0 && accbg != 0.0f) atomicAdd(&g_bg[b], accbg);
}

// ---------------- K1b: fold per-CTA partials into g_acc ----------------
// One warp per (b, id*10+slot) row of 288 contiguous floats.
__global__ void __launch_bounds__(32) k_sum() {
    int r = blockIdx.x;               // 0 .. NBATCH*160-1
    int b = r / (NID * 10);
    int s = r % (NID * 10);
    const float* row = g_part[b][s];
    int lane = threadIdx.x;
    float acc = 0.0f;
    for (int i = lane; i < NCHUNK; i += 32) acc += row[i];
    #pragma unroll
    for (int off = 16; off > 0; off >>= 1)
        acc += __shfl_down_sync(0xffffffffu, acc, off);
    if (lane == 0) g_acc[b * NID + s / 10][s % 10] = acc;
}

// ---------------- K2: finalize per-pair stats ----------------
__global__ void k_finalize() {
    int p = threadIdx.x;
    if (p >= NPAIR) return;
    float cnt  = g_acc[p][0];
    float ex   = (cnt > 0.0f) ? 1.0f : 0.0f;
    float safe = fmaxf(cnt, 1.0f);
    float var  = 0.0f;
    #pragma unroll
    for (int k = 0; k < 3; k++) {
        float c  = g_acc[p][1 + k] / safe;
        float mu = g_acc[p][4 + k] / safe;
        var += g_acc[p][7 + k] - cnt * mu * mu;
        g_center[p][k] = c;
        g_sexp[p][k]   = __expf(10.0f * mu);
    }
    g_var[p]    = ex * (var / (3.0f * safe));
    g_exists[p] = ex;
}

// ---------------- K3: fused dist / seed-loss / error-histogram pass ----------------
__global__ void __launch_bounds__(256) k_dist(const float* __restrict__ pred,
                                              const int*   __restrict__ inst) {
    __shared__ float sc[NID][8];     // cx,cy,cz, e0,e1,e2, exists, pad
    __shared__ float sseed[NID];
    int b = blockIdx.y;
    if (threadIdx.x < NID * 7) {
        int id = threadIdx.x / 7, c = threadIdx.x % 7;
        float v;
        if (c < 3)      v = g_center[b * NID + id][c];
        else if (c < 6) v = g_sexp[b * NID + id][c - 3];
        else            v = g_exists[b * NID + id];
        sc[id][c] = v;
    }
    if (threadIdx.x < NID) sseed[threadIdx.x] = 0.0f;
    __syncthreads();

    const float* pb = pred + (size_t)b * 7 * DHW;
    const int*   ib = inst + (size_t)b * DHW;
    unsigned* negH = g_negH + (size_t)b * NID * NB;
    unsigned* posH = g_posH + (size_t)b * NID * NB;
    int base = blockIdx.x * CHUNK;

    for (int k = 0; k < CHUNK / 256; k++) {
        int v = base + k * 256 + threadIdx.x;
        float x, y, z;
        coords_(v, x, y, z);
        float se0 = tanhf(pb[v])           + x;
        float se1 = tanhf(pb[DHW + v])     + y;
        float se2 = tanhf(pb[2 * DHW + v]) + z;
        float seed = sigmoidf_(pb[6 * DHW + v]);
        int   ii = ib[v];

        #pragma unroll
        for (int id = 0; id < NID; id++) {
            if (sc[id][6] == 0.0f) continue;
            float dx = se0 - sc[id][0];
            float dy = se1 - sc[id][1];
            float dz = se2 - sc[id][2];
            float t = fmaf(dx * dx, sc[id][3],
                      fmaf(dy * dy, sc[id][4],
                           dz * dz * sc[id][5]));
            float d = __expf(-t);
            bool pos = (ii == id + 1);
            float e = pos ? (2.0f - 2.0f * d) : (2.0f * d);
            int bin = (int)(e * INV_W);
            bin = min(bin, NB - 1);
            if (pos) {
                atomicAdd(&posH[id * NB + bin], 1u);
                float dv = seed - d;
                atomicAdd(&sseed[id], dv * dv);
            } else {
                atomicAdd(&negH[id * NB + bin], 1u);
            }
        }
    }
    __syncthreads();
    if (threadIdx.x < NID && sseed[threadIdx.x] != 0.0f)
        atomicAdd(&g_seedl[b * NID + threadIdx.x], sseed[threadIdx.x]);
}

// ---------------- K4: Lovasz via descending-bin scan (one block per pair) ----------------
__global__ void __launch_bounds__(256) k_lovasz() {
    int p = blockIdx.x;                         // 0..63
    __shared__ unsigned sp[256], sn[256];
    __shared__ unsigned op[257], on[257];
    __shared__ double  part[256];
    const unsigned* posH = g_posH + (size_t)p * NB;
    const unsigned* negH = g_negH + (size_t)p * NB;
    int t = threadIdx.x;
    const int CB = NB / 256;                    // 256 bins per thread

    // Phase 1: local sums over this thread's descending-e chunk
    unsigned lp = 0, ln = 0;
    for (int i = 0; i < CB; i++) {
        int bin = (NB - 1) - (t * CB + i);
        lp += posH[bin];
        ln += negH[bin];
    }
    sp[t] = lp; sn[t] = ln;
    __syncthreads();
    if (t == 0) {
        unsigned ap = 0, an = 0;
        for (int i = 0; i < 256; i++) { op[i] = ap; on[i] = an; ap += sp[i]; an += sn[i]; }
        op[256] = ap; on[256] = an;
    }
    __syncthreads();

    double contrib = 0.0;
    unsigned Pu = op[256];
    if (Pu > 0) {
        double P = (double)Pu;
        unsigned cp = op[t], cn = on[t];
        double Jprev = 1.0 - (P - (double)cp) / (P + (double)cn);  // = 0 when cp=cn=0
        for (int i = 0; i < CB; i++) {
            int bin = (NB - 1) - (t * CB + i);
            unsigned np = posH[bin], nn = negH[bin];
            if (np | nn) {
                cp += np; cn += nn;
                double J = 1.0 - (P - (double)cp) / (P + (double)cn);
                double eb = ((double)bin + 0.5) * (1.0 / 32768.0);
                contrib += eb * (J - Jprev);
                Jprev = J;
            }
        }
    }
    part[t] = contrib;
    __syncthreads();
    for (int s = 128; s > 0; s >>= 1) {
        if (t < s) part[t] += part[t + s];
        __syncthreads();
    }
    if (t == 0) g_instl[p] = part[0];
}

// ---------------- K5: assemble the 4 outputs ----------------
__global__ void k_final(float* __restrict__ out) {
    if (threadIdx.x != 0) return;
    double li = 0.0, lv = 0.0, ls = 0.0;
    for (int b = 0; b < NBATCH; b++) {
        double obj = 0.0, vv = 0.0, il = 0.0, sl = 0.0;
        for (int id = 0; id < NID; id++) {
            int p = b * NID + id;
            obj += (double)g_exists[p];
            vv  += (double)g_var[p];
            il  += g_instl[p];
            sl  += (double)g_seedl[p];
        }
        double denom = fmax(obj, 1.0);
        li += il / denom;
        lv += vv / denom;
        ls += (sl + (double)g_bg[b]) / (double)DHW;
    }
    li = li / NBATCH;                 // W_INST = 1
    lv = lv * 10.0 / NBATCH;          // W_VAR = 10
    ls = ls / NBATCH;                 // W_SEED = 1
    out[0] = (float)li;
    out[1] = (float)lv;
    out[2] = (float)ls;
    out[3] = (float)(li + lv + ls);
}

// ---------------- launch ----------------
extern "C" void kernel_launch(void* const* d_in, const int* in_sizes, int n_in,
                              void* d_out, int out_size) {
    const float* pred   = (const float*)d_in[0];   // (B,7,D,H,W)
    const int*   inst   = (const int*)d_in[1];     // (B,D,H,W)
    const int*   labels = (const int*)d_in[2];     // (B,D,H,W)
    // d_in[3] center_images — unused by the reference loss
    // d_in[4] xyzm — computed analytically on device
    float* out = (float*)d_out;

    k_zero<<<2048, 256>>>();
    dim3 g(NCHUNK, NBATCH);
    k_stats<<<g, 256>>>(pred, inst, labels);
    k_sum<<<NBATCH * NID * 10, 32>>>();
    k_finalize<<<1, 64>>>();
    k_dist<<<g, 256>>>(pred, inst);
    k_lovasz<<<NPAIR, 256>>>();
    k_final<<<1, 32>>>(out);
}